// round 15
// baseline (speedup 1.0000x reference)
#include <cuda_runtime.h>
#include <math.h>
#include <stdint.h>

#define QLEN 1024
#define BSZ  4
#define EDIM 1024
#define NH   16
#define DH   64
#define SCALE_F 0.125f
#define LN_EPS 1e-5f

#define MB (QLEN * BSZ)
#define HDIM (3 * NH * DH)        // 3072

// ---------------- scratch (device globals: allocation-free) ----------------
__device__ float g_heads_r[(size_t)MB * HDIM];
__device__ float g_heads_p[(size_t)MB * HDIM];
__device__ float g_rk[(size_t)QLEN * NH * DH];
__device__ float g_vecr[(size_t)MB * EDIM];
__device__ float g_vecp[(size_t)MB * EDIM];
__device__ float g_yr[(size_t)MB * EDIM];
__device__ float g_yp[(size_t)MB * EDIM];

__device__ __forceinline__ void cp_async16(uint32_t dst, const void* src) {
    asm volatile("cp.async.ca.shared.global [%0], [%1], 16;\n" :: "r"(dst), "l"(src));
}
__device__ __forceinline__ void mma_tf32(
    float& c0, float& c1, float& c2, float& c3,
    uint32_t a0, uint32_t a1, uint32_t a2, uint32_t a3,
    uint32_t b0, uint32_t b1)
{
    asm volatile(
        "mma.sync.aligned.m16n8k8.row.col.f32.tf32.tf32.f32 "
        "{%0,%1,%2,%3}, {%4,%5,%6,%7}, {%8,%9}, {%0,%1,%2,%3};\n"
        : "+f"(c0), "+f"(c1), "+f"(c2), "+f"(c3)
        : "r"(a0), "r"(a1), "r"(a2), "r"(a3), "r"(b0), "r"(b1));
}
__device__ __forceinline__ void ldsm_x4(
    uint32_t& r0, uint32_t& r1, uint32_t& r2, uint32_t& r3, uint32_t addr)
{
    asm volatile("ldmatrix.sync.aligned.m8n8.x4.shared.b16 {%0,%1,%2,%3}, [%4];\n"
        : "=r"(r0), "=r"(r1), "=r"(r2), "=r"(r3) : "r"(addr));
}
__device__ __forceinline__ float sqrt_approx(float x) {
    float y;
    asm("sqrt.approx.f32 %0, %1;" : "=f"(y) : "f"(x));
    return y;
}

// ======= TF32 GEMM core (R10-proven: 4-warp tiling + ldmatrix) =============
#define SLAB_ROW 36
#define SLAB_FLOATS (128 * SLAB_ROW)
#define GEMM_SMEM_BYTES (4 * SLAB_FLOATS * 4)   // 73728 B

__device__ __forceinline__ void gemm_core(
    const float* __restrict__ A, const float* __restrict__ B,
    const float* __restrict__ R, float* __restrict__ C,
    int M, int N, int K, float* sm)
{
    const uint32_t sbase = (uint32_t)__cvta_generic_to_shared(sm);
    const int tid = threadIdx.x;
    const int lane = tid & 31, warp = tid >> 5;
    const int g = lane >> 2, tg = lane & 3;
    const int lr = lane & 7, lm = lane >> 3;
    const int wm = warp >> 1, wn = warp & 1;
    const int m0 = blockIdx.y * 128, n0 = blockIdx.x * 128;

    const int stA[2] = {0, 2 * SLAB_FLOATS};
    const int stB[2] = {SLAB_FLOATS, 3 * SLAB_FLOATS};

    const uint32_t aoff = (uint32_t)((wm * 64 + (lm & 1) * 8 + lr) * SLAB_ROW) * 4u
                        + (uint32_t)(lm >> 1) * 16u;
    const uint32_t boff = (uint32_t)((wn * 64 + (lm >> 1) * 8 + lr) * SLAB_ROW) * 4u
                        + (uint32_t)(lm & 1) * 16u;

    float c[4][8][4];
    #pragma unroll
    for (int mi = 0; mi < 4; mi++)
        #pragma unroll
        for (int ni = 0; ni < 8; ni++)
            #pragma unroll
            for (int q = 0; q < 4; q++) c[mi][ni][q] = 0.f;

    const int NS = K / 32;
    auto load_slab = [&](int s, int st) {
        const int k0 = s * 32;
        #pragma unroll
        for (int u = 0; u < 8; u++) {
            int e = tid + u * 128;
            int m = e >> 3, kg = e & 7;
            cp_async16(sbase + (uint32_t)(stA[st] + m * SLAB_ROW + kg * 4) * 4u,
                       A + (size_t)(m0 + m) * K + k0 + kg * 4);
            cp_async16(sbase + (uint32_t)(stB[st] + m * SLAB_ROW + kg * 4) * 4u,
                       B + (size_t)(n0 + m) * K + k0 + kg * 4);
        }
        asm volatile("cp.async.commit_group;\n");
    };

    load_slab(0, 0);
    for (int s = 0; s < NS; s++) {
        const int st = s & 1;
        if (s + 1 < NS) { load_slab(s + 1, st ^ 1); asm volatile("cp.async.wait_group 1;\n"); }
        else            { asm volatile("cp.async.wait_group 0;\n"); }
        __syncthreads();

        const uint32_t aBase = sbase + (uint32_t)stA[st] * 4u + aoff;
        const uint32_t bBase = sbase + (uint32_t)stB[st] * 4u + boff;
        #pragma unroll
        for (int kk = 0; kk < 4; kk++) {
            uint32_t a[4][4], b[8][2];
            #pragma unroll
            for (int mi = 0; mi < 4; mi++)
                ldsm_x4(a[mi][0], a[mi][1], a[mi][2], a[mi][3],
                        aBase + (uint32_t)mi * (16 * SLAB_ROW * 4) + (uint32_t)kk * 32u);
            #pragma unroll
            for (int p = 0; p < 4; p++)
                ldsm_x4(b[2 * p][0], b[2 * p][1], b[2 * p + 1][0], b[2 * p + 1][1],
                        bBase + (uint32_t)p * (16 * SLAB_ROW * 4) + (uint32_t)kk * 32u);
            #pragma unroll
            for (int mi = 0; mi < 4; mi++)
                #pragma unroll
                for (int ni = 0; ni < 8; ni++)
                    mma_tf32(c[mi][ni][0], c[mi][ni][1], c[mi][ni][2], c[mi][ni][3],
                             a[mi][0], a[mi][1], a[mi][2], a[mi][3],
                             b[ni][0], b[ni][1]);
        }
        __syncthreads();
    }

    #pragma unroll
    for (int mi = 0; mi < 4; mi++) {
        int r0 = m0 + wm * 64 + mi * 16 + g;
        #pragma unroll
        for (int ni = 0; ni < 8; ni++) {
            int cc = n0 + wn * 64 + ni * 8 + 2 * tg;
            float2 v0 = make_float2(c[mi][ni][0], c[mi][ni][1]);
            float2 v1 = make_float2(c[mi][ni][2], c[mi][ni][3]);
            if (R) {
                float2 u0 = *(const float2*)&R[(size_t)r0 * N + cc];
                float2 u1 = *(const float2*)&R[(size_t)(r0 + 8) * N + cc];
                v0.x += u0.x; v0.y += u0.y; v1.x += u1.x; v1.y += u1.y;
            }
            *(float2*)&C[(size_t)r0 * N + cc] = v0;
            *(float2*)&C[(size_t)(r0 + 8) * N + cc] = v1;
        }
    }
}

__global__ void __launch_bounds__(128) tf32_gemm_qkvr(
    const float* __restrict__ w_real, const float* __restrict__ w_phase,
    const float* __restrict__ W_qkv,  const float* __restrict__ W_qkv1,
    float* __restrict__ heads_r, float* __restrict__ heads_p,
    const float* __restrict__ r, const float* __restrict__ W_r,
    float* __restrict__ rkb)
{
    extern __shared__ float sm[];
    if (blockIdx.z == 0)      gemm_core(w_real,  W_qkv,  nullptr, heads_r, MB, HDIM, EDIM, sm);
    else if (blockIdx.z == 1) gemm_core(w_phase, W_qkv1, nullptr, heads_p, MB, HDIM, EDIM, sm);
    else if (blockIdx.x < 8 && blockIdx.y < 8)
                              gemm_core(r, W_r, nullptr, rkb, QLEN, NH * DH, EDIM, sm);
}

__global__ void __launch_bounds__(128) tf32_gemm_dual(
    const float* __restrict__ A0, const float* __restrict__ A1,
    const float* __restrict__ B0, const float* __restrict__ B1,
    const float* __restrict__ R0, const float* __restrict__ R1,
    float* __restrict__ C0, float* __restrict__ C1,
    int M, int N, int K)
{
    extern __shared__ float sm[];
    if (blockIdx.z == 0) gemm_core(A0, B0, R0, C0, M, N, K, sm);
    else                 gemm_core(A1, B1, R1, C1, M, N, K, sm);
}

// ======= fused attention: band-reuse + reduced barriers + K prefetch =======
#define AK_QR   0                    // 64x68
#define AK_QP   4352
#define AK_KR   8704
#define AK_KP   13056
#define AK_RK   17408                // 64x68 (new rows only)
#define AK_V    21760                // 64x136
#define AK_E0R  30464                // half buffers, 64x68 each
#define AK_E1R  34816
#define AK_E0P  39168
#define AK_E1P  43520
#define AK_P    47872                // 64x68
#define AK_MISC 52224
#define AK_WKR  (AK_MISC)            // 64
#define AK_WKP  (AK_MISC + 64)       // 64
#define AK_BRK  (AK_MISC + 128)      // 2 x 64 (ping-pong halves)
#define AK_RWB  (AK_MISC + 256)
#define AK_RRB  (AK_MISC + 320)
#define AK_MRUN (AK_MISC + 384)
#define AK_LRUN (AK_MISC + 448)
#define AK_MT   (AK_MISC + 512)      // 4x64
#define AK_LT   (AK_MISC + 768)      // 4x64
#define AK_FLOATS (AK_MISC + 1024)   // 53248
#define AK_SMEM_BYTES (AK_FLOATS * 4) // 212992 B

__global__ void __launch_bounds__(512) attn_fused_kernel(
    const float* __restrict__ hr, const float* __restrict__ hp,
    const float* __restrict__ rk, const float* __restrict__ rwb,
    const float* __restrict__ rrb,
    float* __restrict__ vecr, float* __restrict__ vecp)
{
    extern __shared__ float sm[];
    const uint32_t sbase = (uint32_t)__cvta_generic_to_shared(sm);
    const int it = blockIdx.x;
    const int bn = blockIdx.y;
    const int b = bn >> 4, n = bn & 15;
    const int i0 = it * 64;
    const int tid = threadIdx.x;
    const int lane = tid & 31, warp = tid >> 5;
    const int g = lane >> 2, tg = lane & 3;
    const int wm = warp >> 2, wn = warp & 3;     // 4x4 warp grid
    const int rloc0 = 16 * wm + g;
    const int base0 = 960 - i0;                  // tile0 lower-window base

    // K-group issuer: kr, kp, NEW rk rows for tile jt (own commit group)
    auto issue_K = [&](int jt) {
        const int j0 = jt * 64;
        #pragma unroll
        for (int u = 0; u < 2; u++) {
            int e = tid + u * 512;
            int row = e >> 4, f4 = (e & 15) * 4;
            size_t koff = (size_t)((j0 + row) * 4 + b) * HDIM + 1024 + n * 64 + f4;
            cp_async16(sbase + (uint32_t)(AK_KR + row * 68 + f4) * 4u, hr + koff);
            cp_async16(sbase + (uint32_t)(AK_KP + row * 68 + f4) * 4u, hp + koff);
        }
        #pragma unroll
        for (int u = 0; u < 2; u++) {
            int e = tid + u * 512;
            int row = e >> 4, f4 = (e & 15) * 4;
            int krow = base0 + j0 + 64 + row; krow = krow > 1023 ? 1023 : krow;
            cp_async16(sbase + (uint32_t)(AK_RK + row * 68 + f4) * 4u,
                       rk + (size_t)krow * (NH * DH) + n * 64 + f4);
        }
        asm volatile("cp.async.commit_group;\n");
    };

    // ---- prologue loads: q tiles + bootstrap rk window + biases ----
    #pragma unroll
    for (int u = 0; u < 2; u++) {
        int e = tid + u * 512;
        int row = e >> 4, f4 = (e & 15) * 4;
        size_t qoff = (size_t)((i0 + row) * 4 + b) * HDIM + n * 64 + f4;
        cp_async16(sbase + (uint32_t)(AK_QR + row * 68 + f4) * 4u, hr + qoff);
        cp_async16(sbase + (uint32_t)(AK_QP + row * 68 + f4) * 4u, hp + qoff);
    }
    #pragma unroll
    for (int u = 0; u < 2; u++) {
        int e = tid + u * 512;
        int row = e >> 4, f4 = (e & 15) * 4;
        cp_async16(sbase + (uint32_t)(AK_RK + row * 68 + f4) * 4u,
                   rk + (size_t)(base0 + row) * (NH * DH) + n * 64 + f4);
    }
    asm volatile("cp.async.commit_group;\n");
    if (tid < 64)        sm[AK_RWB + tid] = rwb[n * 64 + tid];
    else if (tid < 128)  sm[AK_RRB + (tid - 64)] = rrb[n * 64 + (tid - 64)];
    else if (tid < 192)  { sm[AK_MRUN + (tid - 128)] = -1e30f; sm[AK_LRUN + (tid - 128)] = 0.f; }
    asm volatile("cp.async.wait_group 0;\n");
    __syncthreads();

    // ---- bootstrap: BRK half1 (pair-split) + E half1 (tile0's lower) ----
    if (tid < 128) {
        int idx = tid >> 1, half = tid & 1;
        int dof = half * 32;
        float s = 0.f;
        #pragma unroll 8
        for (int d = 0; d < 32; d++)
            s += sm[AK_RRB + dof + d] * sm[AK_RK + idx * 68 + dof + d];
        s += __shfl_xor_sync(0xffffffffu, s, 1);
        if (!half) sm[AK_BRK + 64 + idx] = s;
    }
    {
        float B1[2][4] = {}, B2[2][4] = {};
        #pragma unroll
        for (int kk = 0; kk < 8; kk++) {
            int arow = rloc0 * 68 + kk * 8 + tg;
            uint32_t aqr0 = __float_as_uint(sm[AK_QR + arow]);
            uint32_t aqr1 = __float_as_uint(sm[AK_QR + arow + 8 * 68]);
            uint32_t aqr2 = __float_as_uint(sm[AK_QR + arow + 4]);
            uint32_t aqr3 = __float_as_uint(sm[AK_QR + arow + 8 * 68 + 4]);
            uint32_t aqp0 = __float_as_uint(sm[AK_QP + arow]);
            uint32_t aqp1 = __float_as_uint(sm[AK_QP + arow + 8 * 68]);
            uint32_t aqp2 = __float_as_uint(sm[AK_QP + arow + 4]);
            uint32_t aqp3 = __float_as_uint(sm[AK_QP + arow + 8 * 68 + 4]);
            #pragma unroll
            for (int li = 0; li < 2; li++) {
                int rrow = (16 * wn + 8 * li + g) * 68 + kk * 8 + tg;
                uint32_t br0 = __float_as_uint(sm[AK_RK + rrow]);
                uint32_t br1 = __float_as_uint(sm[AK_RK + rrow + 4]);
                mma_tf32(B1[li][0], B1[li][1], B1[li][2], B1[li][3],
                         aqr0, aqr1, aqr2, aqr3, br0, br1);
                mma_tf32(B2[li][0], B2[li][1], B2[li][2], B2[li][3],
                         aqp0, aqp1, aqp2, aqp3, br0, br1);
            }
        }
        #pragma unroll
        for (int li = 0; li < 2; li++) {
            #pragma unroll
            for (int q = 0; q < 4; q++) {
                int row = rloc0 + 8 * (q >> 1);
                int col = 16 * wn + 8 * li + 2 * tg + (q & 1);
                sm[AK_E1R + row * 68 + col] = B1[li][q];
                sm[AK_E1P + row * 68 + col] = B2[li][q];
            }
        }
    }
    __syncthreads();   // bootstrap RK reads done -> safe to prefetch K(0)
    issue_K(0);

    float O[4][4];
    #pragma unroll
    for (int ni = 0; ni < 4; ni++)
        #pragma unroll
        for (int q = 0; q < 4; q++) O[ni][q] = 0.f;

    for (int jt = 0; jt <= it; jt++) {
        const int j0 = jt * 64;
        const bool diag = (jt == it);
        const int nb = jt & 1;
        const int ERn = AK_E0R + nb * 4352, ERo = AK_E0R + (nb ^ 1) * 4352;
        const int EPn = AK_E0P + nb * 4352, EPo = AK_E0P + (nb ^ 1) * 4352;

        __syncthreads();   // prior PV reads of V done -> safe to overwrite V

        // ---- V load (blocking; K(jt) already in flight) ----
        #pragma unroll
        for (int u = 0; u < 4; u++) {
            int e = tid + u * 512;
            int row = e >> 5, cc = (e & 31) * 4;
            size_t voff = (size_t)((j0 + row) * 4 + b) * HDIM + 2048 + n * 64;
            const float* src = (cc < 64) ? (hr + voff + cc) : (hp + voff + (cc - 64));
            cp_async16(sbase + (uint32_t)(AK_V + row * 136 + cc) * 4u, src);
        }
        asm volatile("cp.async.commit_group;\n");
        asm volatile("cp.async.wait_group 0;\n");   // K(jt) + V(jt)
        __syncthreads();

        // ---- bias vectors (pair-split, 384 threads), then straight to mma ----
        if (tid < 384) {
            int which = tid >> 7;
            int idx = (tid & 127) >> 1, half = tid & 1;
            int dof = half * 32;
            float s = 0.f;
            if (which == 0) {
                #pragma unroll 8
                for (int d = 0; d < 32; d++)
                    s += sm[AK_RWB + dof + d] * sm[AK_KR + idx * 68 + dof + d];
            } else if (which == 1) {
                #pragma unroll 8
                for (int d = 0; d < 32; d++)
                    s += sm[AK_RWB + dof + d] * sm[AK_KP + idx * 68 + dof + d];
            } else {
                #pragma unroll 8
                for (int d = 0; d < 32; d++)
                    s += sm[AK_RRB + dof + d] * sm[AK_RK + idx * 68 + dof + d];
            }
            s += __shfl_xor_sync(0xffffffffu, s, 1);
            if (!half) {
                if (which == 0)      sm[AK_WKR + idx] = s;
                else if (which == 1) sm[AK_WKP + idx] = s;
                else                 sm[AK_BRK + nb * 64 + idx] = s;
            }
        }
        // (no barrier: mma reads only KR/KP/RK; bias outputs fenced by (b))

        // ---- mma pass: 3 AC + 2 BD(new half) ----
        float A1[2][4] = {}, A2[2][4] = {}, A3[2][4] = {};
        float B1[2][4] = {}, B2[2][4] = {};

        #pragma unroll
        for (int kk = 0; kk < 8; kk++) {
            int arow = rloc0 * 68 + kk * 8 + tg;
            uint32_t aqr0 = __float_as_uint(sm[AK_QR + arow]);
            uint32_t aqr1 = __float_as_uint(sm[AK_QR + arow + 8 * 68]);
            uint32_t aqr2 = __float_as_uint(sm[AK_QR + arow + 4]);
            uint32_t aqr3 = __float_as_uint(sm[AK_QR + arow + 8 * 68 + 4]);
            uint32_t aqp0 = __float_as_uint(sm[AK_QP + arow]);
            uint32_t aqp1 = __float_as_uint(sm[AK_QP + arow + 8 * 68]);
            uint32_t aqp2 = __float_as_uint(sm[AK_QP + arow + 4]);
            uint32_t aqp3 = __float_as_uint(sm[AK_QP + arow + 8 * 68 + 4]);

            #pragma unroll
            for (int ni = 0; ni < 2; ni++) {
                int brow = (16 * wn + 8 * ni + g) * 68 + kk * 8 + tg;
                uint32_t bkr0 = __float_as_uint(sm[AK_KR + brow]);
                uint32_t bkr1 = __float_as_uint(sm[AK_KR + brow + 4]);
                uint32_t bkp0 = __float_as_uint(sm[AK_KP + brow]);
                uint32_t bkp1 = __float_as_uint(sm[AK_KP + brow + 4]);
                mma_tf32(A1[ni][0], A1[ni][1], A1[ni][2], A1[ni][3],
                         aqr0, aqr1, aqr2, aqr3, bkr0, bkr1);
                mma_tf32(A2[ni][0], A2[ni][1], A2[ni][2], A2[ni][3],
                         aqp0, aqp1, aqp2, aqp3, bkp0, bkp1);
                mma_tf32(A3[ni][0], A3[ni][1], A3[ni][2], A3[ni][3],
                         aqr0, aqr1, aqr2, aqr3, bkp0, bkp1);
            }
            #pragma unroll
            for (int li = 0; li < 2; li++) {
                int rrow = (16 * wn + 8 * li + g) * 68 + kk * 8 + tg;
                uint32_t br0 = __float_as_uint(sm[AK_RK + rrow]);
                uint32_t br1 = __float_as_uint(sm[AK_RK + rrow + 4]);
                mma_tf32(B1[li][0], B1[li][1], B1[li][2], B1[li][3],
                         aqr0, aqr1, aqr2, aqr3, br0, br1);
                mma_tf32(B2[li][0], B2[li][1], B2[li][2], B2[li][3],
                         aqp0, aqp1, aqp2, aqp3, br0, br1);
            }
        }

        // ---- stage new E half, then prefetch K(jt+1) ----
        #pragma unroll
        for (int li = 0; li < 2; li++) {
            #pragma unroll
            for (int q = 0; q < 4; q++) {
                int row = rloc0 + 8 * (q >> 1);
                int col = 16 * wn + 8 * li + 2 * tg + (q & 1);
                sm[ERn + row * 68 + col] = B1[li][q];
                sm[EPn + row * 68 + col] = B2[li][q];
            }
        }
        __syncthreads();   // (b): mma reads of KR/KP/RK done + E visible
        if (jt + 1 <= it) issue_K(jt + 1);   // overlaps combine/softmax/PV

        // ---- combine into scores (approx sqrt) ----
        float sv[2][4];
        #pragma unroll
        for (int ni = 0; ni < 2; ni++) {
            #pragma unroll
            for (int q = 0; q < 4; q++) {
                int row = rloc0 + 8 * (q >> 1);
                int col = 16 * wn + 8 * ni + 2 * tg + (q & 1);
                float wkp_c = sm[AK_WKP + col];
                float acr = A1[ni][q] + sm[AK_WKR + col] - A2[ni][q] - wkp_c;
                float acp = 2.0f * (A3[ni][q] + wkp_c);
                int L = col - row + 63;
                float bb, e1, e2;
                if (L < 64) {
                    bb = sm[AK_BRK + (nb ^ 1) * 64 + L];
                    e1 = sm[ERo + row * 68 + L];
                    e2 = sm[EPo + row * 68 + L];
                } else {
                    bb = sm[AK_BRK + nb * 64 + (L - 64)];
                    e1 = sm[ERn + row * 68 + (L - 64)];
                    e2 = sm[EPn + row * 68 + (L - 64)];
                }
                float b1v = e1 + bb;
                float b2v = e2 + bb;
                float s = (sqrt_approx(acr * acr + acp * acp)
                         + sqrt_approx(b1v * b1v + b2v * b2v)) * SCALE_F;
                if (diag && col > row) s = -1e30f;
                sv[ni][q] = s;
            }
        }

        // ---- online softmax ----
        float pm[2] = {-1e30f, -1e30f};
        #pragma unroll
        for (int ni = 0; ni < 2; ni++) {
            #pragma unroll
            for (int q = 0; q < 4; q++) pm[q >> 1] = fmaxf(pm[q >> 1], sv[ni][q]);
        }
        #pragma unroll
        for (int rh = 0; rh < 2; rh++) {
            pm[rh] = fmaxf(pm[rh], __shfl_xor_sync(0xffffffffu, pm[rh], 1));
            pm[rh] = fmaxf(pm[rh], __shfl_xor_sync(0xffffffffu, pm[rh], 2));
        }
        sm[AK_MT + wn * 64 + rloc0]     = pm[0];
        sm[AK_MT + wn * 64 + rloc0 + 8] = pm[1];
        __syncthreads();   // (c)

        float mold[2], mnew[2], alpha[2], psum[2] = {0.f, 0.f};
        #pragma unroll
        for (int rh = 0; rh < 2; rh++) {
            int r = rloc0 + 8 * rh;
            mold[rh] = sm[AK_MRUN + r];
            float mt = fmaxf(fmaxf(sm[AK_MT + r], sm[AK_MT + 64 + r]),
                             fmaxf(sm[AK_MT + 128 + r], sm[AK_MT + 192 + r]));
            mnew[rh] = fmaxf(mold[rh], mt);
            alpha[rh] = __expf(mold[rh] - mnew[rh]);
        }
        #pragma unroll
        for (int ni = 0; ni < 2; ni++) {
            #pragma unroll
            for (int q = 0; q < 4; q++) {
                int rh = q >> 1;
                int row = rloc0 + 8 * rh;
                int col = 16 * wn + 8 * ni + 2 * tg + (q & 1);
                float p = __expf(sv[ni][q] - mnew[rh]);
                psum[rh] += p;
                sm[AK_P + row * 68 + col] = p;
            }
        }
        #pragma unroll
        for (int rh = 0; rh < 2; rh++) {
            psum[rh] += __shfl_xor_sync(0xffffffffu, psum[rh], 1);
            psum[rh] += __shfl_xor_sync(0xffffffffu, psum[rh], 2);
        }
        sm[AK_LT + wn * 64 + rloc0]     = psum[0];
        sm[AK_LT + wn * 64 + rloc0 + 8] = psum[1];
        #pragma unroll
        for (int ni = 0; ni < 4; ni++) {
            #pragma unroll
            for (int q = 0; q < 4; q++) O[ni][q] *= alpha[q >> 1];
        }
        __syncthreads();   // (d)

        if (wn == 0 && tg == 0) {
            #pragma unroll
            for (int rh = 0; rh < 2; rh++) {
                int r = rloc0 + 8 * rh;
                sm[AK_MRUN + r] = mnew[rh];
                sm[AK_LRUN + r] = sm[AK_LRUN + r] * alpha[rh]
                                  + sm[AK_LT + r] + sm[AK_LT + 64 + r]
                                  + sm[AK_LT + 128 + r] + sm[AK_LT + 192 + r];
            }
        }

        // ---- PV mma: O += P(64x64) @ V(64x128) ----
        #pragma unroll
        for (int kk = 0; kk < 8; kk++) {
            int arow = rloc0 * 68 + kk * 8 + tg;
            uint32_t a0 = __float_as_uint(sm[AK_P + arow]);
            uint32_t a1 = __float_as_uint(sm[AK_P + arow + 8 * 68]);
            uint32_t a2 = __float_as_uint(sm[AK_P + arow + 4]);
            uint32_t a3 = __float_as_uint(sm[AK_P + arow + 8 * 68 + 4]);
            #pragma unroll
            for (int ni = 0; ni < 4; ni++) {
                int ch = 32 * wn + 8 * ni + g;
                uint32_t b0 = __float_as_uint(sm[AK_V + (kk * 8 + tg) * 136 + ch]);
                uint32_t b1 = __float_as_uint(sm[AK_V + (kk * 8 + tg + 4) * 136 + ch]);
                mma_tf32(O[ni][0], O[ni][1], O[ni][2], O[ni][3],
                         a0, a1, a2, a3, b0, b1);
            }
        }
    }

    __syncthreads();
    float linv[2] = {1.f / sm[AK_LRUN + rloc0], 1.f / sm[AK_LRUN + rloc0 + 8]};
    float* dst = (wn < 2) ? vecr : vecp;
    const int colbase = (32 * wn) & 63;
    #pragma unroll
    for (int ni = 0; ni < 4; ni++) {
        int ch = colbase + 8 * ni + 2 * tg;
        int r0 = i0 + rloc0;
        size_t o0 = (size_t)(r0 * 4 + b) * EDIM + n * 64 + ch;
        size_t o1 = (size_t)((r0 + 8) * 4 + b) * EDIM + n * 64 + ch;
        *(float2*)&dst[o0] = make_float2(O[ni][0] * linv[0], O[ni][1] * linv[0]);
        *(float2*)&dst[o1] = make_float2(O[ni][2] * linv[1], O[ni][3] * linv[1]);
    }
}

// ---------------- LayerNorm (vectorized, 1 global read) --------------------
__global__ void __launch_bounds__(256) ln2_kernel(
    const float* __restrict__ yr, const float* __restrict__ yp,
    const float* __restrict__ g, const float* __restrict__ be,
    float* __restrict__ out)
{
    const int row = blockIdx.x;
    const float* y = (blockIdx.y ? yp : yr) + (size_t)row * EDIM;
    float* o = out + (size_t)blockIdx.y * MB * EDIM + (size_t)row * EDIM;
    const int tid = threadIdx.x;
    const int lane = tid & 31, warp = tid >> 5;
    __shared__ float ws[8];
    __shared__ float s_mu, s_rstd;

    float4 v = ((const float4*)y)[tid];
    float s = v.x + v.y + v.z + v.w;
    #pragma unroll
    for (int off = 16; off > 0; off >>= 1) s += __shfl_xor_sync(0xffffffffu, s, off);
    if (lane == 0) ws[warp] = s;
    __syncthreads();
    if (tid == 0) {
        float t = 0.f;
        #pragma unroll
        for (int w = 0; w < 8; w++) t += ws[w];
        s_mu = t * (1.f / EDIM);
    }
    __syncthreads();
    const float mu = s_mu;

    float dx = v.x - mu, dy = v.y - mu, dz = v.z - mu, dw = v.w - mu;
    float sq = dx * dx + dy * dy + dz * dz + dw * dw;
    #pragma unroll
    for (int off = 16; off > 0; off >>= 1) sq += __shfl_xor_sync(0xffffffffu, sq, off);
    if (lane == 0) ws[warp] = sq;
    __syncthreads();
    if (tid == 0) {
        float t = 0.f;
        #pragma unroll
        for (int w = 0; w < 8; w++) t += ws[w];
        s_rstd = rsqrtf(t * (1.f / EDIM) + LN_EPS);
    }
    __syncthreads();
    const float rstd = s_rstd;

    float4 gv = ((const float4*)g)[tid];
    float4 bv = ((const float4*)be)[tid];
    float4 rr;
    rr.x = dx * rstd * gv.x + bv.x;
    rr.y = dy * rstd * gv.y + bv.y;
    rr.z = dz * rstd * gv.z + bv.z;
    rr.w = dw * rstd * gv.w + bv.w;
    ((float4*)o)[tid] = rr;
}

// ---------------- launch ---------------------------------------------------
extern "C" void kernel_launch(void* const* d_in, const int* in_sizes, int n_in,
                              void* d_out, int out_size)
{
    (void)in_sizes; (void)n_in; (void)out_size;
    const float* w_real  = (const float*)d_in[0];
    const float* w_phase = (const float*)d_in[1];
    const float* r       = (const float*)d_in[2];
    const float* r_w_b   = (const float*)d_in[3];
    const float* r_r_b   = (const float*)d_in[4];
    const float* W_qkv   = (const float*)d_in[5];
    const float* W_qkv1  = (const float*)d_in[6];
    const float* W_r     = (const float*)d_in[7];
    const float* W_o     = (const float*)d_in[8];
    const float* W_o1    = (const float*)d_in[9];
    const float* gamma   = (const float*)d_in[10];
    const float* beta    = (const float*)d_in[11];

    float *heads_r, *heads_p, *rkb, *vecr, *vecp, *yr, *yp;
    cudaGetSymbolAddress((void**)&heads_r, g_heads_r);
    cudaGetSymbolAddress((void**)&heads_p, g_heads_p);
    cudaGetSymbolAddress((void**)&rkb,     g_rk);
    cudaGetSymbolAddress((void**)&vecr,    g_vecr);
    cudaGetSymbolAddress((void**)&vecp,    g_vecp);
    cudaGetSymbolAddress((void**)&yr,      g_yr);
    cudaGetSymbolAddress((void**)&yp,      g_yp);

    cudaFuncSetAttribute(tf32_gemm_qkvr, cudaFuncAttributeMaxDynamicSharedMemorySize, GEMM_SMEM_BYTES);
    cudaFuncSetAttribute(tf32_gemm_dual, cudaFuncAttributeMaxDynamicSharedMemorySize, GEMM_SMEM_BYTES);
    cudaFuncSetAttribute(attn_fused_kernel, cudaFuncAttributeMaxDynamicSharedMemorySize, AK_SMEM_BYTES);

    // QKV projections (both streams) + r projection, single launch
    tf32_gemm_qkvr<<<dim3(HDIM / 128, MB / 128, 3), 128, GEMM_SMEM_BYTES>>>(
        w_real, w_phase, W_qkv, W_qkv1, heads_r, heads_p, r, W_r, rkb);

    // fused attention: band-reuse + approx sqrt + reduced barriers + K prefetch
    attn_fused_kernel<<<dim3(16, 64), 512, AK_SMEM_BYTES>>>(
        heads_r, heads_p, rkb, r_w_b, r_r_b, vecr, vecp);

    // output projections with residual (both streams, one launch), then LN
    tf32_gemm_dual<<<dim3(EDIM / 128, MB / 128, 2), 128, GEMM_SMEM_BYTES>>>(
        vecr, vecp, W_o, W_o1, w_real, w_phase, yr, yp, MB, EDIM, EDIM);

    float* out = (float*)d_out;
    ln2_kernel<<<dim3(MB, 2), 256>>>(yr, yp, gamma, beta, out);
}

// round 16
// speedup vs baseline: 1.0219x; 1.0219x over previous
#include <cuda_runtime.h>
#include <math.h>
#include <stdint.h>

#define QLEN 1024
#define BSZ  4
#define EDIM 1024
#define NH   16
#define DH   64
#define SCALE_F 0.125f
#define LN_EPS 1e-5f

#define MB (QLEN * BSZ)
#define HDIM (3 * NH * DH)        // 3072

// ---------------- scratch (device globals: allocation-free) ----------------
__device__ float g_heads_r[(size_t)MB * HDIM];
__device__ float g_heads_p[(size_t)MB * HDIM];
__device__ float g_rk[(size_t)QLEN * NH * DH];
__device__ float g_vecr[(size_t)MB * EDIM];
__device__ float g_vecp[(size_t)MB * EDIM];
__device__ float g_yr[(size_t)MB * EDIM];
__device__ float g_yp[(size_t)MB * EDIM];

__device__ __forceinline__ void cp_async16(uint32_t dst, const void* src) {
    asm volatile("cp.async.ca.shared.global [%0], [%1], 16;\n" :: "r"(dst), "l"(src));
}
__device__ __forceinline__ void mma_tf32(
    float& c0, float& c1, float& c2, float& c3,
    uint32_t a0, uint32_t a1, uint32_t a2, uint32_t a3,
    uint32_t b0, uint32_t b1)
{
    asm volatile(
        "mma.sync.aligned.m16n8k8.row.col.f32.tf32.tf32.f32 "
        "{%0,%1,%2,%3}, {%4,%5,%6,%7}, {%8,%9}, {%0,%1,%2,%3};\n"
        : "+f"(c0), "+f"(c1), "+f"(c2), "+f"(c3)
        : "r"(a0), "r"(a1), "r"(a2), "r"(a3), "r"(b0), "r"(b1));
}
__device__ __forceinline__ void ldsm_x4(
    uint32_t& r0, uint32_t& r1, uint32_t& r2, uint32_t& r3, uint32_t addr)
{
    asm volatile("ldmatrix.sync.aligned.m8n8.x4.shared.b16 {%0,%1,%2,%3}, [%4];\n"
        : "=r"(r0), "=r"(r1), "=r"(r2), "=r"(r3) : "r"(addr));
}
__device__ __forceinline__ float sqrt_approx(float x) {
    float y;
    asm("sqrt.approx.f32 %0, %1;" : "=f"(y) : "f"(x));
    return y;
}

// ======= TF32 GEMM core (R10-proven: 4-warp tiling + ldmatrix) =============
#define SLAB_ROW 36
#define SLAB_FLOATS (128 * SLAB_ROW)
#define GEMM_SMEM_BYTES (4 * SLAB_FLOATS * 4)   // 73728 B

__device__ __forceinline__ void gemm_core(
    const float* __restrict__ A, const float* __restrict__ B,
    const float* __restrict__ R, float* __restrict__ C,
    int M, int N, int K, float* sm)
{
    const uint32_t sbase = (uint32_t)__cvta_generic_to_shared(sm);
    const int tid = threadIdx.x;
    const int lane = tid & 31, warp = tid >> 5;
    const int g = lane >> 2, tg = lane & 3;
    const int lr = lane & 7, lm = lane >> 3;
    const int wm = warp >> 1, wn = warp & 1;
    const int m0 = blockIdx.y * 128, n0 = blockIdx.x * 128;

    const int stA[2] = {0, 2 * SLAB_FLOATS};
    const int stB[2] = {SLAB_FLOATS, 3 * SLAB_FLOATS};

    const uint32_t aoff = (uint32_t)((wm * 64 + (lm & 1) * 8 + lr) * SLAB_ROW) * 4u
                        + (uint32_t)(lm >> 1) * 16u;
    const uint32_t boff = (uint32_t)((wn * 64 + (lm >> 1) * 8 + lr) * SLAB_ROW) * 4u
                        + (uint32_t)(lm & 1) * 16u;

    float c[4][8][4];
    #pragma unroll
    for (int mi = 0; mi < 4; mi++)
        #pragma unroll
        for (int ni = 0; ni < 8; ni++)
            #pragma unroll
            for (int q = 0; q < 4; q++) c[mi][ni][q] = 0.f;

    const int NS = K / 32;
    auto load_slab = [&](int s, int st) {
        const int k0 = s * 32;
        #pragma unroll
        for (int u = 0; u < 8; u++) {
            int e = tid + u * 128;
            int m = e >> 3, kg = e & 7;
            cp_async16(sbase + (uint32_t)(stA[st] + m * SLAB_ROW + kg * 4) * 4u,
                       A + (size_t)(m0 + m) * K + k0 + kg * 4);
            cp_async16(sbase + (uint32_t)(stB[st] + m * SLAB_ROW + kg * 4) * 4u,
                       B + (size_t)(n0 + m) * K + k0 + kg * 4);
        }
        asm volatile("cp.async.commit_group;\n");
    };

    load_slab(0, 0);
    for (int s = 0; s < NS; s++) {
        const int st = s & 1;
        if (s + 1 < NS) { load_slab(s + 1, st ^ 1); asm volatile("cp.async.wait_group 1;\n"); }
        else            { asm volatile("cp.async.wait_group 0;\n"); }
        __syncthreads();

        const uint32_t aBase = sbase + (uint32_t)stA[st] * 4u + aoff;
        const uint32_t bBase = sbase + (uint32_t)stB[st] * 4u + boff;
        #pragma unroll
        for (int kk = 0; kk < 4; kk++) {
            uint32_t a[4][4], b[8][2];
            #pragma unroll
            for (int mi = 0; mi < 4; mi++)
                ldsm_x4(a[mi][0], a[mi][1], a[mi][2], a[mi][3],
                        aBase + (uint32_t)mi * (16 * SLAB_ROW * 4) + (uint32_t)kk * 32u);
            #pragma unroll
            for (int p = 0; p < 4; p++)
                ldsm_x4(b[2 * p][0], b[2 * p][1], b[2 * p + 1][0], b[2 * p + 1][1],
                        bBase + (uint32_t)p * (16 * SLAB_ROW * 4) + (uint32_t)kk * 32u);
            #pragma unroll
            for (int mi = 0; mi < 4; mi++)
                #pragma unroll
                for (int ni = 0; ni < 8; ni++)
                    mma_tf32(c[mi][ni][0], c[mi][ni][1], c[mi][ni][2], c[mi][ni][3],
                             a[mi][0], a[mi][1], a[mi][2], a[mi][3],
                             b[ni][0], b[ni][1]);
        }
        __syncthreads();
    }

    #pragma unroll
    for (int mi = 0; mi < 4; mi++) {
        int r0 = m0 + wm * 64 + mi * 16 + g;
        #pragma unroll
        for (int ni = 0; ni < 8; ni++) {
            int cc = n0 + wn * 64 + ni * 8 + 2 * tg;
            float2 v0 = make_float2(c[mi][ni][0], c[mi][ni][1]);
            float2 v1 = make_float2(c[mi][ni][2], c[mi][ni][3]);
            if (R) {
                float2 u0 = *(const float2*)&R[(size_t)r0 * N + cc];
                float2 u1 = *(const float2*)&R[(size_t)(r0 + 8) * N + cc];
                v0.x += u0.x; v0.y += u0.y; v1.x += u1.x; v1.y += u1.y;
            }
            *(float2*)&C[(size_t)r0 * N + cc] = v0;
            *(float2*)&C[(size_t)(r0 + 8) * N + cc] = v1;
        }
    }
}

__global__ void __launch_bounds__(128) tf32_gemm_qkvr(
    const float* __restrict__ w_real, const float* __restrict__ w_phase,
    const float* __restrict__ W_qkv,  const float* __restrict__ W_qkv1,
    float* __restrict__ heads_r, float* __restrict__ heads_p,
    const float* __restrict__ r, const float* __restrict__ W_r,
    float* __restrict__ rkb)
{
    extern __shared__ float sm[];
    if (blockIdx.z == 0)      gemm_core(w_real,  W_qkv,  nullptr, heads_r, MB, HDIM, EDIM, sm);
    else if (blockIdx.z == 1) gemm_core(w_phase, W_qkv1, nullptr, heads_p, MB, HDIM, EDIM, sm);
    else if (blockIdx.x < 8 && blockIdx.y < 8)
                              gemm_core(r, W_r, nullptr, rkb, QLEN, NH * DH, EDIM, sm);
}

__global__ void __launch_bounds__(128) tf32_gemm_dual(
    const float* __restrict__ A0, const float* __restrict__ A1,
    const float* __restrict__ B0, const float* __restrict__ B1,
    const float* __restrict__ R0, const float* __restrict__ R1,
    float* __restrict__ C0, float* __restrict__ C1,
    int M, int N, int K)
{
    extern __shared__ float sm[];
    if (blockIdx.z == 0) gemm_core(A0, B0, R0, C0, M, N, K, sm);
    else                 gemm_core(A1, B1, R1, C1, M, N, K, sm);
}

// ======= fused attention: R14-proven (band-reuse + approx sqrt), minus the
//         redundant bias->mma barrier (single change this round) ============
#define AK_QR   0                    // 64x68
#define AK_QP   4352
#define AK_KR   8704
#define AK_KP   13056
#define AK_RK   17408                // 64x68 (new rows only)
#define AK_V    21760                // 64x136
#define AK_E0R  30464                // half buffers, 64x68 each
#define AK_E1R  34816
#define AK_E0P  39168
#define AK_E1P  43520
#define AK_P    47872                // 64x68
#define AK_MISC 52224
#define AK_WKR  (AK_MISC)            // 64
#define AK_WKP  (AK_MISC + 64)       // 64
#define AK_BRK  (AK_MISC + 128)      // 2 x 64 (ping-pong halves)
#define AK_RWB  (AK_MISC + 256)
#define AK_RRB  (AK_MISC + 320)
#define AK_MRUN (AK_MISC + 384)
#define AK_LRUN (AK_MISC + 448)
#define AK_MT   (AK_MISC + 512)      // 4x64
#define AK_LT   (AK_MISC + 768)      // 4x64
#define AK_FLOATS (AK_MISC + 1024)   // 53248
#define AK_SMEM_BYTES (AK_FLOATS * 4) // 212992 B

__global__ void __launch_bounds__(512) attn_fused_kernel(
    const float* __restrict__ hr, const float* __restrict__ hp,
    const float* __restrict__ rk, const float* __restrict__ rwb,
    const float* __restrict__ rrb,
    float* __restrict__ vecr, float* __restrict__ vecp)
{
    extern __shared__ float sm[];
    const uint32_t sbase = (uint32_t)__cvta_generic_to_shared(sm);
    const int it = blockIdx.x;
    const int bn = blockIdx.y;
    const int b = bn >> 4, n = bn & 15;
    const int i0 = it * 64;
    const int tid = threadIdx.x;
    const int lane = tid & 31, warp = tid >> 5;
    const int g = lane >> 2, tg = lane & 3;
    const int wm = warp >> 2, wn = warp & 3;     // 4x4 warp grid
    const int rloc0 = 16 * wm + g;
    const int base0 = 960 - i0;                  // tile0 lower-window base

    // ---- prologue loads: q tiles + bootstrap rk window + biases ----
    #pragma unroll
    for (int u = 0; u < 2; u++) {
        int e = tid + u * 512;
        int row = e >> 4, f4 = (e & 15) * 4;
        size_t qoff = (size_t)((i0 + row) * 4 + b) * HDIM + n * 64 + f4;
        cp_async16(sbase + (uint32_t)(AK_QR + row * 68 + f4) * 4u, hr + qoff);
        cp_async16(sbase + (uint32_t)(AK_QP + row * 68 + f4) * 4u, hp + qoff);
    }
    #pragma unroll
    for (int u = 0; u < 2; u++) {
        int e = tid + u * 512;
        int row = e >> 4, f4 = (e & 15) * 4;
        cp_async16(sbase + (uint32_t)(AK_RK + row * 68 + f4) * 4u,
                   rk + (size_t)(base0 + row) * (NH * DH) + n * 64 + f4);
    }
    asm volatile("cp.async.commit_group;\n");
    if (tid < 64)        sm[AK_RWB + tid] = rwb[n * 64 + tid];
    else if (tid < 128)  sm[AK_RRB + (tid - 64)] = rrb[n * 64 + (tid - 64)];
    else if (tid < 192)  { sm[AK_MRUN + (tid - 128)] = -1e30f; sm[AK_LRUN + (tid - 128)] = 0.f; }
    asm volatile("cp.async.wait_group 0;\n");
    __syncthreads();

    // ---- bootstrap: BRK half1 + E half1 (tile0's lower half) ----
    if (tid < 64) {
        float s = 0.f;
        #pragma unroll 8
        for (int d = 0; d < 64; d++) s += sm[AK_RRB + d] * sm[AK_RK + tid * 68 + d];
        sm[AK_BRK + 64 + tid] = s;
    }
    {
        float B1[2][4] = {}, B2[2][4] = {};
        #pragma unroll
        for (int kk = 0; kk < 8; kk++) {
            int arow = rloc0 * 68 + kk * 8 + tg;
            uint32_t aqr0 = __float_as_uint(sm[AK_QR + arow]);
            uint32_t aqr1 = __float_as_uint(sm[AK_QR + arow + 8 * 68]);
            uint32_t aqr2 = __float_as_uint(sm[AK_QR + arow + 4]);
            uint32_t aqr3 = __float_as_uint(sm[AK_QR + arow + 8 * 68 + 4]);
            uint32_t aqp0 = __float_as_uint(sm[AK_QP + arow]);
            uint32_t aqp1 = __float_as_uint(sm[AK_QP + arow + 8 * 68]);
            uint32_t aqp2 = __float_as_uint(sm[AK_QP + arow + 4]);
            uint32_t aqp3 = __float_as_uint(sm[AK_QP + arow + 8 * 68 + 4]);
            #pragma unroll
            for (int li = 0; li < 2; li++) {
                int rrow = (16 * wn + 8 * li + g) * 68 + kk * 8 + tg;
                uint32_t br0 = __float_as_uint(sm[AK_RK + rrow]);
                uint32_t br1 = __float_as_uint(sm[AK_RK + rrow + 4]);
                mma_tf32(B1[li][0], B1[li][1], B1[li][2], B1[li][3],
                         aqr0, aqr1, aqr2, aqr3, br0, br1);
                mma_tf32(B2[li][0], B2[li][1], B2[li][2], B2[li][3],
                         aqp0, aqp1, aqp2, aqp3, br0, br1);
            }
        }
        #pragma unroll
        for (int li = 0; li < 2; li++) {
            #pragma unroll
            for (int q = 0; q < 4; q++) {
                int row = rloc0 + 8 * (q >> 1);
                int col = 16 * wn + 8 * li + 2 * tg + (q & 1);
                sm[AK_E1R + row * 68 + col] = B1[li][q];
                sm[AK_E1P + row * 68 + col] = B2[li][q];
            }
        }
    }

    float O[4][4];
    #pragma unroll
    for (int ni = 0; ni < 4; ni++)
        #pragma unroll
        for (int q = 0; q < 4; q++) O[ni][q] = 0.f;

    for (int jt = 0; jt <= it; jt++) {
        const int j0 = jt * 64;
        const bool diag = (jt == it);
        const int nb = jt & 1;                     // new half buffer
        const int ERn = AK_E0R + nb * 4352, ERo = AK_E0R + (nb ^ 1) * 4352;
        const int EPn = AK_E0P + nb * 4352, EPo = AK_E0P + (nb ^ 1) * 4352;

        __syncthreads();   // prior tile fully consumed (incl. bootstrap mma reads of RK)

        // ---- loads: kr, kp, NEW rk rows (base+64..+127), V ----
        #pragma unroll
        for (int u = 0; u < 2; u++) {
            int e = tid + u * 512;
            int row = e >> 4, f4 = (e & 15) * 4;
            size_t koff = (size_t)((j0 + row) * 4 + b) * HDIM + 1024 + n * 64 + f4;
            cp_async16(sbase + (uint32_t)(AK_KR + row * 68 + f4) * 4u, hr + koff);
            cp_async16(sbase + (uint32_t)(AK_KP + row * 68 + f4) * 4u, hp + koff);
        }
        #pragma unroll
        for (int u = 0; u < 2; u++) {
            int e = tid + u * 512;
            int row = e >> 4, f4 = (e & 15) * 4;
            int krow = base0 + j0 + 64 + row; krow = krow > 1023 ? 1023 : krow;
            cp_async16(sbase + (uint32_t)(AK_RK + row * 68 + f4) * 4u,
                       rk + (size_t)krow * (NH * DH) + n * 64 + f4);
        }
        #pragma unroll
        for (int u = 0; u < 4; u++) {
            int e = tid + u * 512;
            int row = e >> 5, cc = (e & 31) * 4;
            size_t voff = (size_t)((j0 + row) * 4 + b) * HDIM + 2048 + n * 64;
            const float* src = (cc < 64) ? (hr + voff + cc) : (hp + voff + (cc - 64));
            cp_async16(sbase + (uint32_t)(AK_V + row * 136 + cc) * 4u, src);
        }
        asm volatile("cp.async.commit_group;\n");
        asm volatile("cp.async.wait_group 0;\n");
        __syncthreads();

        // ---- bias vectors: WKR, WKP, new BRK half (no barrier after:
        //      mma reads only KR/KP/RK; bias outputs fenced by (a)+(b)) ----
        if (tid < 64) {
            float s = 0.f;
            #pragma unroll 8
            for (int d = 0; d < 64; d++) s += sm[AK_RWB + d] * sm[AK_KR + tid * 68 + d];
            sm[AK_WKR + tid] = s;
        } else if (tid < 128) {
            int j = tid - 64; float s = 0.f;
            #pragma unroll 8
            for (int d = 0; d < 64; d++) s += sm[AK_RWB + d] * sm[AK_KP + j * 68 + d];
            sm[AK_WKP + j] = s;
        } else if (tid < 192) {
            int L = tid - 128; float s = 0.f;
            #pragma unroll 8
            for (int d = 0; d < 64; d++) s += sm[AK_RRB + d] * sm[AK_RK + L * 68 + d];
            sm[AK_BRK + nb * 64 + L] = s;
        }

        // ---- mma pass: 3 AC products + 2 BD products (new half only) ----
        float A1[2][4] = {}, A2[2][4] = {}, A3[2][4] = {};
        float B1[2][4] = {}, B2[2][4] = {};

        #pragma unroll
        for (int kk = 0; kk < 8; kk++) {
            int arow = rloc0 * 68 + kk * 8 + tg;
            uint32_t aqr0 = __float_as_uint(sm[AK_QR + arow]);
            uint32_t aqr1 = __float_as_uint(sm[AK_QR + arow + 8 * 68]);
            uint32_t aqr2 = __float_as_uint(sm[AK_QR + arow + 4]);
            uint32_t aqr3 = __float_as_uint(sm[AK_QR + arow + 8 * 68 + 4]);
            uint32_t aqp0 = __float_as_uint(sm[AK_QP + arow]);
            uint32_t aqp1 = __float_as_uint(sm[AK_QP + arow + 8 * 68]);
            uint32_t aqp2 = __float_as_uint(sm[AK_QP + arow + 4]);
            uint32_t aqp3 = __float_as_uint(sm[AK_QP + arow + 8 * 68 + 4]);

            #pragma unroll
            for (int ni = 0; ni < 2; ni++) {
                int brow = (16 * wn + 8 * ni + g) * 68 + kk * 8 + tg;
                uint32_t bkr0 = __float_as_uint(sm[AK_KR + brow]);
                uint32_t bkr1 = __float_as_uint(sm[AK_KR + brow + 4]);
                uint32_t bkp0 = __float_as_uint(sm[AK_KP + brow]);
                uint32_t bkp1 = __float_as_uint(sm[AK_KP + brow + 4]);
                mma_tf32(A1[ni][0], A1[ni][1], A1[ni][2], A1[ni][3],
                         aqr0, aqr1, aqr2, aqr3, bkr0, bkr1);
                mma_tf32(A2[ni][0], A2[ni][1], A2[ni][2], A2[ni][3],
                         aqp0, aqp1, aqp2, aqp3, bkp0, bkp1);
                mma_tf32(A3[ni][0], A3[ni][1], A3[ni][2], A3[ni][3],
                         aqr0, aqr1, aqr2, aqr3, bkp0, bkp1);
            }
            #pragma unroll
            for (int li = 0; li < 2; li++) {
                int rrow = (16 * wn + 8 * li + g) * 68 + kk * 8 + tg;
                uint32_t br0 = __float_as_uint(sm[AK_RK + rrow]);
                uint32_t br1 = __float_as_uint(sm[AK_RK + rrow + 4]);
                mma_tf32(B1[li][0], B1[li][1], B1[li][2], B1[li][3],
                         aqr0, aqr1, aqr2, aqr3, br0, br1);
                mma_tf32(B2[li][0], B2[li][1], B2[li][2], B2[li][3],
                         aqp0, aqp1, aqp2, aqp3, br0, br1);
            }
        }

        // ---- stage new E half ----
        __syncthreads();   // (a) old-half combine reads from previous tile done
        #pragma unroll
        for (int li = 0; li < 2; li++) {
            #pragma unroll
            for (int q = 0; q < 4; q++) {
                int row = rloc0 + 8 * (q >> 1);
                int col = 16 * wn + 8 * li + 2 * tg + (q & 1);
                sm[ERn + row * 68 + col] = B1[li][q];
                sm[EPn + row * 68 + col] = B2[li][q];
            }
        }
        __syncthreads();   // (b)

        // ---- combine into scores (approx sqrt) ----
        float sv[2][4];
        #pragma unroll
        for (int ni = 0; ni < 2; ni++) {
            #pragma unroll
            for (int q = 0; q < 4; q++) {
                int row = rloc0 + 8 * (q >> 1);
                int col = 16 * wn + 8 * ni + 2 * tg + (q & 1);
                float wkp_c = sm[AK_WKP + col];
                float acr = A1[ni][q] + sm[AK_WKR + col] - A2[ni][q] - wkp_c;
                float acp = 2.0f * (A3[ni][q] + wkp_c);
                int L = col - row + 63;
                float bb, e1, e2;
                if (L < 64) {
                    bb = sm[AK_BRK + (nb ^ 1) * 64 + L];
                    e1 = sm[ERo + row * 68 + L];
                    e2 = sm[EPo + row * 68 + L];
                } else {
                    bb = sm[AK_BRK + nb * 64 + (L - 64)];
                    e1 = sm[ERn + row * 68 + (L - 64)];
                    e2 = sm[EPn + row * 68 + (L - 64)];
                }
                float b1v = e1 + bb;
                float b2v = e2 + bb;
                float s = (sqrt_approx(acr * acr + acp * acp)
                         + sqrt_approx(b1v * b1v + b2v * b2v)) * SCALE_F;
                if (diag && col > row) s = -1e30f;
                sv[ni][q] = s;
            }
        }

        // ---- online softmax ----
        float pm[2] = {-1e30f, -1e30f};
        #pragma unroll
        for (int ni = 0; ni < 2; ni++) {
            #pragma unroll
            for (int q = 0; q < 4; q++) pm[q >> 1] = fmaxf(pm[q >> 1], sv[ni][q]);
        }
        #pragma unroll
        for (int rh = 0; rh < 2; rh++) {
            pm[rh] = fmaxf(pm[rh], __shfl_xor_sync(0xffffffffu, pm[rh], 1));
            pm[rh] = fmaxf(pm[rh], __shfl_xor_sync(0xffffffffu, pm[rh], 2));
        }
        sm[AK_MT + wn * 64 + rloc0]     = pm[0];
        sm[AK_MT + wn * 64 + rloc0 + 8] = pm[1];
        __syncthreads();   // (c)

        float mold[2], mnew[2], alpha[2], psum[2] = {0.f, 0.f};
        #pragma unroll
        for (int rh = 0; rh < 2; rh++) {
            int r = rloc0 + 8 * rh;
            mold[rh] = sm[AK_MRUN + r];
            float mt = fmaxf(fmaxf(sm[AK_MT + r], sm[AK_MT + 64 + r]),
                             fmaxf(sm[AK_MT + 128 + r], sm[AK_MT + 192 + r]));
            mnew[rh] = fmaxf(mold[rh], mt);
            alpha[rh] = __expf(mold[rh] - mnew[rh]);
        }
        #pragma unroll
        for (int ni = 0; ni < 2; ni++) {
            #pragma unroll
            for (int q = 0; q < 4; q++) {
                int rh = q >> 1;
                int row = rloc0 + 8 * rh;
                int col = 16 * wn + 8 * ni + 2 * tg + (q & 1);
                float p = __expf(sv[ni][q] - mnew[rh]);
                psum[rh] += p;
                sm[AK_P + row * 68 + col] = p;
            }
        }
        #pragma unroll
        for (int rh = 0; rh < 2; rh++) {
            psum[rh] += __shfl_xor_sync(0xffffffffu, psum[rh], 1);
            psum[rh] += __shfl_xor_sync(0xffffffffu, psum[rh], 2);
        }
        sm[AK_LT + wn * 64 + rloc0]     = psum[0];
        sm[AK_LT + wn * 64 + rloc0 + 8] = psum[1];
        #pragma unroll
        for (int ni = 0; ni < 4; ni++) {
            #pragma unroll
            for (int q = 0; q < 4; q++) O[ni][q] *= alpha[q >> 1];
        }
        __syncthreads();   // (d)

        if (wn == 0 && tg == 0) {
            #pragma unroll
            for (int rh = 0; rh < 2; rh++) {
                int r = rloc0 + 8 * rh;
                sm[AK_MRUN + r] = mnew[rh];
                sm[AK_LRUN + r] = sm[AK_LRUN + r] * alpha[rh]
                                  + sm[AK_LT + r] + sm[AK_LT + 64 + r]
                                  + sm[AK_LT + 128 + r] + sm[AK_LT + 192 + r];
            }
        }

        // ---- PV mma: O += P(64x64) @ V(64x128) ----
        #pragma unroll
        for (int kk = 0; kk < 8; kk++) {
            int arow = rloc0 * 68 + kk * 8 + tg;
            uint32_t a0 = __float_as_uint(sm[AK_P + arow]);
            uint32_t a1 = __float_as_uint(sm[AK_P + arow + 8 * 68]);
            uint32_t a2 = __float_as_uint(sm[AK_P + arow + 4]);
            uint32_t a3 = __float_as_uint(sm[AK_P + arow + 8 * 68 + 4]);
            #pragma unroll
            for (int ni = 0; ni < 4; ni++) {
                int ch = 32 * wn + 8 * ni + g;
                uint32_t b0 = __float_as_uint(sm[AK_V + (kk * 8 + tg) * 136 + ch]);
                uint32_t b1 = __float_as_uint(sm[AK_V + (kk * 8 + tg + 4) * 136 + ch]);
                mma_tf32(O[ni][0], O[ni][1], O[ni][2], O[ni][3],
                         a0, a1, a2, a3, b0, b1);
            }
        }
    }

    __syncthreads();
    float linv[2] = {1.f / sm[AK_LRUN + rloc0], 1.f / sm[AK_LRUN + rloc0 + 8]};
    float* dst = (wn < 2) ? vecr : vecp;
    const int colbase = (32 * wn) & 63;
    #pragma unroll
    for (int ni = 0; ni < 4; ni++) {
        int ch = colbase + 8 * ni + 2 * tg;
        int r0 = i0 + rloc0;
        size_t o0 = (size_t)(r0 * 4 + b) * EDIM + n * 64 + ch;
        size_t o1 = (size_t)((r0 + 8) * 4 + b) * EDIM + n * 64 + ch;
        *(float2*)&dst[o0] = make_float2(O[ni][0] * linv[0], O[ni][1] * linv[0]);
        *(float2*)&dst[o1] = make_float2(O[ni][2] * linv[1], O[ni][3] * linv[1]);
    }
}

// ---------------- LayerNorm (vectorized, 1 global read) --------------------
__global__ void __launch_bounds__(256) ln2_kernel(
    const float* __restrict__ yr, const float* __restrict__ yp,
    const float* __restrict__ g, const float* __restrict__ be,
    float* __restrict__ out)
{
    const int row = blockIdx.x;
    const float* y = (blockIdx.y ? yp : yr) + (size_t)row * EDIM;
    float* o = out + (size_t)blockIdx.y * MB * EDIM + (size_t)row * EDIM;
    const int tid = threadIdx.x;
    const int lane = tid & 31, warp = tid >> 5;
    __shared__ float ws[8];
    __shared__ float s_mu, s_rstd;

    float4 v = ((const float4*)y)[tid];
    float s = v.x + v.y + v.z + v.w;
    #pragma unroll
    for (int off = 16; off > 0; off >>= 1) s += __shfl_xor_sync(0xffffffffu, s, off);
    if (lane == 0) ws[warp] = s;
    __syncthreads();
    if (tid == 0) {
        float t = 0.f;
        #pragma unroll
        for (int w = 0; w < 8; w++) t += ws[w];
        s_mu = t * (1.f / EDIM);
    }
    __syncthreads();
    const float mu = s_mu;

    float dx = v.x - mu, dy = v.y - mu, dz = v.z - mu, dw = v.w - mu;
    float sq = dx * dx + dy * dy + dz * dz + dw * dw;
    #pragma unroll
    for (int off = 16; off > 0; off >>= 1) sq += __shfl_xor_sync(0xffffffffu, sq, off);
    if (lane == 0) ws[warp] = sq;
    __syncthreads();
    if (tid == 0) {
        float t = 0.f;
        #pragma unroll
        for (int w = 0; w < 8; w++) t += ws[w];
        s_rstd = rsqrtf(t * (1.f / EDIM) + LN_EPS);
    }
    __syncthreads();
    const float rstd = s_rstd;

    float4 gv = ((const float4*)g)[tid];
    float4 bv = ((const float4*)be)[tid];
    float4 rr;
    rr.x = dx * rstd * gv.x + bv.x;
    rr.y = dy * rstd * gv.y + bv.y;
    rr.z = dz * rstd * gv.z + bv.z;
    rr.w = dw * rstd * gv.w + bv.w;
    ((float4*)o)[tid] = rr;
}

// ---------------- launch ---------------------------------------------------
extern "C" void kernel_launch(void* const* d_in, const int* in_sizes, int n_in,
                              void* d_out, int out_size)
{
    (void)in_sizes; (void)n_in; (void)out_size;
    const float* w_real  = (const float*)d_in[0];
    const float* w_phase = (const float*)d_in[1];
    const float* r       = (const float*)d_in[2];
    const float* r_w_b   = (const float*)d_in[3];
    const float* r_r_b   = (const float*)d_in[4];
    const float* W_qkv   = (const float*)d_in[5];
    const float* W_qkv1  = (const float*)d_in[6];
    const float* W_r     = (const float*)d_in[7];
    const float* W_o     = (const float*)d_in[8];
    const float* W_o1    = (const float*)d_in[9];
    const float* gamma   = (const float*)d_in[10];
    const float* beta    = (const float*)d_in[11];

    float *heads_r, *heads_p, *rkb, *vecr, *vecp, *yr, *yp;
    cudaGetSymbolAddress((void**)&heads_r, g_heads_r);
    cudaGetSymbolAddress((void**)&heads_p, g_heads_p);
    cudaGetSymbolAddress((void**)&rkb,     g_rk);
    cudaGetSymbolAddress((void**)&vecr,    g_vecr);
    cudaGetSymbolAddress((void**)&vecp,    g_vecp);
    cudaGetSymbolAddress((void**)&yr,      g_yr);
    cudaGetSymbolAddress((void**)&yp,      g_yp);

    cudaFuncSetAttribute(tf32_gemm_qkvr, cudaFuncAttributeMaxDynamicSharedMemorySize, GEMM_SMEM_BYTES);
    cudaFuncSetAttribute(tf32_gemm_dual, cudaFuncAttributeMaxDynamicSharedMemorySize, GEMM_SMEM_BYTES);
    cudaFuncSetAttribute(attn_fused_kernel, cudaFuncAttributeMaxDynamicSharedMemorySize, AK_SMEM_BYTES);

    // QKV projections (both streams) + r projection, single launch
    tf32_gemm_qkvr<<<dim3(HDIM / 128, MB / 128, 3), 128, GEMM_SMEM_BYTES>>>(
        w_real, w_phase, W_qkv, W_qkv1, heads_r, heads_p, r, W_r, rkb);

    // fused attention: band-reuse + approx sqrt (R14) minus one barrier
    attn_fused_kernel<<<dim3(16, 64), 512, AK_SMEM_BYTES>>>(
        heads_r, heads_p, rkb, r_w_b, r_r_b, vecr, vecp);

    // output projections with residual (both streams, one launch), then LN
    tf32_gemm_dual<<<dim3(EDIM / 128, MB / 128, 2), 128, GEMM_SMEM_BYTES>>>(
        vecr, vecp, W_o, W_o1, w_real, w_phase, yr, yp, MB, EDIM, EDIM);

    float* out = (float*)d_out;
    ln2_kernel<<<dim3(MB, 2), 256>>>(yr, yp, gamma, beta, out);
}

// round 17
// speedup vs baseline: 1.0280x; 1.0060x over previous
#include <cuda_runtime.h>
#include <math.h>
#include <stdint.h>

#define QLEN 1024
#define BSZ  4
#define EDIM 1024
#define NH   16
#define DH   64
#define SCALE_F 0.125f
#define LN_EPS 1e-5f

#define MB (QLEN * BSZ)
#define HDIM (3 * NH * DH)        // 3072

// ---------------- scratch (device globals: allocation-free) ----------------
__device__ float g_heads_r[(size_t)MB * HDIM];
__device__ float g_heads_p[(size_t)MB * HDIM];
__device__ float g_rk[(size_t)QLEN * NH * DH];
__device__ float g_vecr[(size_t)MB * EDIM];
__device__ float g_vecp[(size_t)MB * EDIM];
__device__ float g_yr[(size_t)MB * EDIM];
__device__ float g_yp[(size_t)MB * EDIM];

__device__ __forceinline__ void cp_async16(uint32_t dst, const void* src) {
    asm volatile("cp.async.ca.shared.global [%0], [%1], 16;\n" :: "r"(dst), "l"(src));
}
__device__ __forceinline__ void mma_tf32(
    float& c0, float& c1, float& c2, float& c3,
    uint32_t a0, uint32_t a1, uint32_t a2, uint32_t a3,
    uint32_t b0, uint32_t b1)
{
    asm volatile(
        "mma.sync.aligned.m16n8k8.row.col.f32.tf32.tf32.f32 "
        "{%0,%1,%2,%3}, {%4,%5,%6,%7}, {%8,%9}, {%0,%1,%2,%3};\n"
        : "+f"(c0), "+f"(c1), "+f"(c2), "+f"(c3)
        : "r"(a0), "r"(a1), "r"(a2), "r"(a3), "r"(b0), "r"(b1));
}
__device__ __forceinline__ void ldsm_x4(
    uint32_t& r0, uint32_t& r1, uint32_t& r2, uint32_t& r3, uint32_t addr)
{
    asm volatile("ldmatrix.sync.aligned.m8n8.x4.shared.b16 {%0,%1,%2,%3}, [%4];\n"
        : "=r"(r0), "=r"(r1), "=r"(r2), "=r"(r3) : "r"(addr));
}
__device__ __forceinline__ float sqrt_approx(float x) {
    float y;
    asm("sqrt.approx.f32 %0, %1;" : "=f"(y) : "f"(x));
    return y;
}

// ======= TF32 GEMM core (R10-proven: 4-warp tiling + ldmatrix) =============
#define SLAB_ROW 36
#define SLAB_FLOATS (128 * SLAB_ROW)
#define GEMM_SMEM_BYTES (4 * SLAB_FLOATS * 4)   // 73728 B

__device__ __forceinline__ void gemm_core(
    const float* __restrict__ A, const float* __restrict__ B,
    const float* __restrict__ R, float* __restrict__ C,
    int M, int N, int K, float* sm)
{
    const uint32_t sbase = (uint32_t)__cvta_generic_to_shared(sm);
    const int tid = threadIdx.x;
    const int lane = tid & 31, warp = tid >> 5;
    const int g = lane >> 2, tg = lane & 3;
    const int lr = lane & 7, lm = lane >> 3;
    const int wm = warp >> 1, wn = warp & 1;
    const int m0 = blockIdx.y * 128, n0 = blockIdx.x * 128;

    const int stA[2] = {0, 2 * SLAB_FLOATS};
    const int stB[2] = {SLAB_FLOATS, 3 * SLAB_FLOATS};

    const uint32_t aoff = (uint32_t)((wm * 64 + (lm & 1) * 8 + lr) * SLAB_ROW) * 4u
                        + (uint32_t)(lm >> 1) * 16u;
    const uint32_t boff = (uint32_t)((wn * 64 + (lm >> 1) * 8 + lr) * SLAB_ROW) * 4u
                        + (uint32_t)(lm & 1) * 16u;

    float c[4][8][4];
    #pragma unroll
    for (int mi = 0; mi < 4; mi++)
        #pragma unroll
        for (int ni = 0; ni < 8; ni++)
            #pragma unroll
            for (int q = 0; q < 4; q++) c[mi][ni][q] = 0.f;

    const int NS = K / 32;
    auto load_slab = [&](int s, int st) {
        const int k0 = s * 32;
        #pragma unroll
        for (int u = 0; u < 8; u++) {
            int e = tid + u * 128;
            int m = e >> 3, kg = e & 7;
            cp_async16(sbase + (uint32_t)(stA[st] + m * SLAB_ROW + kg * 4) * 4u,
                       A + (size_t)(m0 + m) * K + k0 + kg * 4);
            cp_async16(sbase + (uint32_t)(stB[st] + m * SLAB_ROW + kg * 4) * 4u,
                       B + (size_t)(n0 + m) * K + k0 + kg * 4);
        }
        asm volatile("cp.async.commit_group;\n");
    };

    load_slab(0, 0);
    for (int s = 0; s < NS; s++) {
        const int st = s & 1;
        if (s + 1 < NS) { load_slab(s + 1, st ^ 1); asm volatile("cp.async.wait_group 1;\n"); }
        else            { asm volatile("cp.async.wait_group 0;\n"); }
        __syncthreads();

        const uint32_t aBase = sbase + (uint32_t)stA[st] * 4u + aoff;
        const uint32_t bBase = sbase + (uint32_t)stB[st] * 4u + boff;
        #pragma unroll
        for (int kk = 0; kk < 4; kk++) {
            uint32_t a[4][4], b[8][2];
            #pragma unroll
            for (int mi = 0; mi < 4; mi++)
                ldsm_x4(a[mi][0], a[mi][1], a[mi][2], a[mi][3],
                        aBase + (uint32_t)mi * (16 * SLAB_ROW * 4) + (uint32_t)kk * 32u);
            #pragma unroll
            for (int p = 0; p < 4; p++)
                ldsm_x4(b[2 * p][0], b[2 * p][1], b[2 * p + 1][0], b[2 * p + 1][1],
                        bBase + (uint32_t)p * (16 * SLAB_ROW * 4) + (uint32_t)kk * 32u);
            #pragma unroll
            for (int mi = 0; mi < 4; mi++)
                #pragma unroll
                for (int ni = 0; ni < 8; ni++)
                    mma_tf32(c[mi][ni][0], c[mi][ni][1], c[mi][ni][2], c[mi][ni][3],
                             a[mi][0], a[mi][1], a[mi][2], a[mi][3],
                             b[ni][0], b[ni][1]);
        }
        __syncthreads();
    }

    #pragma unroll
    for (int mi = 0; mi < 4; mi++) {
        int r0 = m0 + wm * 64 + mi * 16 + g;
        #pragma unroll
        for (int ni = 0; ni < 8; ni++) {
            int cc = n0 + wn * 64 + ni * 8 + 2 * tg;
            float2 v0 = make_float2(c[mi][ni][0], c[mi][ni][1]);
            float2 v1 = make_float2(c[mi][ni][2], c[mi][ni][3]);
            if (R) {
                float2 u0 = *(const float2*)&R[(size_t)r0 * N + cc];
                float2 u1 = *(const float2*)&R[(size_t)(r0 + 8) * N + cc];
                v0.x += u0.x; v0.y += u0.y; v1.x += u1.x; v1.y += u1.y;
            }
            *(float2*)&C[(size_t)r0 * N + cc] = v0;
            *(float2*)&C[(size_t)(r0 + 8) * N + cc] = v1;
        }
    }
}

__global__ void __launch_bounds__(128) tf32_gemm_qkvr(
    const float* __restrict__ w_real, const float* __restrict__ w_phase,
    const float* __restrict__ W_qkv,  const float* __restrict__ W_qkv1,
    float* __restrict__ heads_r, float* __restrict__ heads_p,
    const float* __restrict__ r, const float* __restrict__ W_r,
    float* __restrict__ rkb)
{
    extern __shared__ float sm[];
    if (blockIdx.z == 0)      gemm_core(w_real,  W_qkv,  nullptr, heads_r, MB, HDIM, EDIM, sm);
    else if (blockIdx.z == 1) gemm_core(w_phase, W_qkv1, nullptr, heads_p, MB, HDIM, EDIM, sm);
    else if (blockIdx.x < 8 && blockIdx.y < 8)
                              gemm_core(r, W_r, nullptr, rkb, QLEN, NH * DH, EDIM, sm);
}

__global__ void __launch_bounds__(128) tf32_gemm_dual(
    const float* __restrict__ A0, const float* __restrict__ A1,
    const float* __restrict__ B0, const float* __restrict__ B1,
    const float* __restrict__ R0, const float* __restrict__ R1,
    float* __restrict__ C0, float* __restrict__ C1,
    int M, int N, int K)
{
    extern __shared__ float sm[];
    if (blockIdx.z == 0) gemm_core(A0, B0, R0, C0, M, N, K, sm);
    else                 gemm_core(A1, B1, R1, C1, M, N, K, sm);
}

// ======= fused attention: R16-proven + ldmatrix fragment feeding ===========
#define AK_QR   0                    // 64x68
#define AK_QP   4352
#define AK_KR   8704
#define AK_KP   13056
#define AK_RK   17408                // 64x68 (new rows only)
#define AK_V    21760                // 64x136
#define AK_E0R  30464                // half buffers, 64x68 each
#define AK_E1R  34816
#define AK_E0P  39168
#define AK_E1P  43520
#define AK_P    47872                // 64x68
#define AK_MISC 52224
#define AK_WKR  (AK_MISC)            // 64
#define AK_WKP  (AK_MISC + 64)       // 64
#define AK_BRK  (AK_MISC + 128)      // 2 x 64 (ping-pong halves)
#define AK_RWB  (AK_MISC + 256)
#define AK_RRB  (AK_MISC + 320)
#define AK_MRUN (AK_MISC + 384)
#define AK_LRUN (AK_MISC + 448)
#define AK_MT   (AK_MISC + 512)      // 4x64
#define AK_LT   (AK_MISC + 768)      // 4x64
#define AK_FLOATS (AK_MISC + 1024)   // 53248
#define AK_SMEM_BYTES (AK_FLOATS * 4) // 212992 B

__global__ void __launch_bounds__(512) attn_fused_kernel(
    const float* __restrict__ hr, const float* __restrict__ hp,
    const float* __restrict__ rk, const float* __restrict__ rwb,
    const float* __restrict__ rrb,
    float* __restrict__ vecr, float* __restrict__ vecp)
{
    extern __shared__ float sm[];
    const uint32_t sbase = (uint32_t)__cvta_generic_to_shared(sm);
    const int it = blockIdx.x;
    const int bn = blockIdx.y;
    const int b = bn >> 4, n = bn & 15;
    const int i0 = it * 64;
    const int tid = threadIdx.x;
    const int lane = tid & 31, warp = tid >> 5;
    const int g = lane >> 2, tg = lane & 3;
    const int lr = lane & 7, lm = lane >> 3;     // ldmatrix address lanes
    const int wm = warp >> 2, wn = warp & 3;     // 4x4 warp grid
    const int rloc0 = 16 * wm + g;
    const int base0 = 960 - i0;                  // tile0 lower-window base

    // ldmatrix per-lane byte offsets (68-float rows: 272B stride, 4-bank
    // shift/row -> 8 rows x 4 banks = conflict-free, same as SLAB_ROW=36):
    // A operand (Q / P): rows 16*wm + (m&1)*8 + lr, 16B chunk (m>>1)
    const uint32_t qa_off = (uint32_t)((16 * wm + (lm & 1) * 8 + lr) * 68) * 4u
                          + (uint32_t)(lm >> 1) * 16u;
    // B operand (KR/KP/RK): rows 16*wn + (m>>1)*8 + lr, 16B chunk (m&1)
    const uint32_t kb_off = (uint32_t)((16 * wn + (lm >> 1) * 8 + lr) * 68) * 4u
                          + (uint32_t)(lm & 1) * 16u;
    const uint32_t aQR = sbase + (uint32_t)AK_QR * 4u + qa_off;
    const uint32_t aQP = sbase + (uint32_t)AK_QP * 4u + qa_off;
    const uint32_t bKR = sbase + (uint32_t)AK_KR * 4u + kb_off;
    const uint32_t bKP = sbase + (uint32_t)AK_KP * 4u + kb_off;
    const uint32_t bRK = sbase + (uint32_t)AK_RK * 4u + kb_off;
    const uint32_t aP  = sbase + (uint32_t)AK_P  * 4u + qa_off;

    // ---- prologue loads: q tiles + bootstrap rk window + biases ----
    #pragma unroll
    for (int u = 0; u < 2; u++) {
        int e = tid + u * 512;
        int row = e >> 4, f4 = (e & 15) * 4;
        size_t qoff = (size_t)((i0 + row) * 4 + b) * HDIM + n * 64 + f4;
        cp_async16(sbase + (uint32_t)(AK_QR + row * 68 + f4) * 4u, hr + qoff);
        cp_async16(sbase + (uint32_t)(AK_QP + row * 68 + f4) * 4u, hp + qoff);
    }
    #pragma unroll
    for (int u = 0; u < 2; u++) {
        int e = tid + u * 512;
        int row = e >> 4, f4 = (e & 15) * 4;
        cp_async16(sbase + (uint32_t)(AK_RK + row * 68 + f4) * 4u,
                   rk + (size_t)(base0 + row) * (NH * DH) + n * 64 + f4);
    }
    asm volatile("cp.async.commit_group;\n");
    if (tid < 64)        sm[AK_RWB + tid] = rwb[n * 64 + tid];
    else if (tid < 128)  sm[AK_RRB + (tid - 64)] = rrb[n * 64 + (tid - 64)];
    else if (tid < 192)  { sm[AK_MRUN + (tid - 128)] = -1e30f; sm[AK_LRUN + (tid - 128)] = 0.f; }
    asm volatile("cp.async.wait_group 0;\n");
    __syncthreads();

    // ---- bootstrap: BRK half1 + E half1 (tile0's lower half) ----
    if (tid < 64) {
        float s = 0.f;
        #pragma unroll 8
        for (int d = 0; d < 64; d++) s += sm[AK_RRB + d] * sm[AK_RK + tid * 68 + d];
        sm[AK_BRK + 64 + tid] = s;
    }
    {
        float B1[2][4] = {}, B2[2][4] = {};
        #pragma unroll
        for (int kk = 0; kk < 8; kk++) {
            uint32_t aqr[4], aqp[4], brk[2][2];
            ldsm_x4(aqr[0], aqr[1], aqr[2], aqr[3], aQR + (uint32_t)kk * 32u);
            ldsm_x4(aqp[0], aqp[1], aqp[2], aqp[3], aQP + (uint32_t)kk * 32u);
            ldsm_x4(brk[0][0], brk[0][1], brk[1][0], brk[1][1], bRK + (uint32_t)kk * 32u);
            #pragma unroll
            for (int li = 0; li < 2; li++) {
                mma_tf32(B1[li][0], B1[li][1], B1[li][2], B1[li][3],
                         aqr[0], aqr[1], aqr[2], aqr[3], brk[li][0], brk[li][1]);
                mma_tf32(B2[li][0], B2[li][1], B2[li][2], B2[li][3],
                         aqp[0], aqp[1], aqp[2], aqp[3], brk[li][0], brk[li][1]);
            }
        }
        #pragma unroll
        for (int li = 0; li < 2; li++) {
            #pragma unroll
            for (int q = 0; q < 4; q++) {
                int row = rloc0 + 8 * (q >> 1);
                int col = 16 * wn + 8 * li + 2 * tg + (q & 1);
                sm[AK_E1R + row * 68 + col] = B1[li][q];
                sm[AK_E1P + row * 68 + col] = B2[li][q];
            }
        }
    }

    float O[4][4];
    #pragma unroll
    for (int ni = 0; ni < 4; ni++)
        #pragma unroll
        for (int q = 0; q < 4; q++) O[ni][q] = 0.f;

    for (int jt = 0; jt <= it; jt++) {
        const int j0 = jt * 64;
        const bool diag = (jt == it);
        const int nb = jt & 1;
        const int ERn = AK_E0R + nb * 4352, ERo = AK_E0R + (nb ^ 1) * 4352;
        const int EPn = AK_E0P + nb * 4352, EPo = AK_E0P + (nb ^ 1) * 4352;

        __syncthreads();   // prior tile fully consumed

        // ---- loads: kr, kp, NEW rk rows, V ----
        #pragma unroll
        for (int u = 0; u < 2; u++) {
            int e = tid + u * 512;
            int row = e >> 4, f4 = (e & 15) * 4;
            size_t koff = (size_t)((j0 + row) * 4 + b) * HDIM + 1024 + n * 64 + f4;
            cp_async16(sbase + (uint32_t)(AK_KR + row * 68 + f4) * 4u, hr + koff);
            cp_async16(sbase + (uint32_t)(AK_KP + row * 68 + f4) * 4u, hp + koff);
        }
        #pragma unroll
        for (int u = 0; u < 2; u++) {
            int e = tid + u * 512;
            int row = e >> 4, f4 = (e & 15) * 4;
            int krow = base0 + j0 + 64 + row; krow = krow > 1023 ? 1023 : krow;
            cp_async16(sbase + (uint32_t)(AK_RK + row * 68 + f4) * 4u,
                       rk + (size_t)krow * (NH * DH) + n * 64 + f4);
        }
        #pragma unroll
        for (int u = 0; u < 4; u++) {
            int e = tid + u * 512;
            int row = e >> 5, cc = (e & 31) * 4;
            size_t voff = (size_t)((j0 + row) * 4 + b) * HDIM + 2048 + n * 64;
            const float* src = (cc < 64) ? (hr + voff + cc) : (hp + voff + (cc - 64));
            cp_async16(sbase + (uint32_t)(AK_V + row * 136 + cc) * 4u, src);
        }
        asm volatile("cp.async.commit_group;\n");
        asm volatile("cp.async.wait_group 0;\n");
        __syncthreads();

        // ---- bias vectors (no trailing barrier: mma reads only KR/KP/RK) ----
        if (tid < 64) {
            float s = 0.f;
            #pragma unroll 8
            for (int d = 0; d < 64; d++) s += sm[AK_RWB + d] * sm[AK_KR + tid * 68 + d];
            sm[AK_WKR + tid] = s;
        } else if (tid < 128) {
            int j = tid - 64; float s = 0.f;
            #pragma unroll 8
            for (int d = 0; d < 64; d++) s += sm[AK_RWB + d] * sm[AK_KP + j * 68 + d];
            sm[AK_WKP + j] = s;
        } else if (tid < 192) {
            int L = tid - 128; float s = 0.f;
            #pragma unroll 8
            for (int d = 0; d < 64; d++) s += sm[AK_RRB + d] * sm[AK_RK + L * 68 + d];
            sm[AK_BRK + nb * 64 + L] = s;
        }

        // ---- mma pass: 3 AC + 2 BD, ldmatrix fragments ----
        float A1[2][4] = {}, A2[2][4] = {}, A3[2][4] = {};
        float B1[2][4] = {}, B2[2][4] = {};

        #pragma unroll
        for (int kk = 0; kk < 8; kk++) {
            uint32_t aqr[4], aqp[4], bkr[2][2], bkp[2][2], brk[2][2];
            ldsm_x4(aqr[0], aqr[1], aqr[2], aqr[3], aQR + (uint32_t)kk * 32u);
            ldsm_x4(aqp[0], aqp[1], aqp[2], aqp[3], aQP + (uint32_t)kk * 32u);
            ldsm_x4(bkr[0][0], bkr[0][1], bkr[1][0], bkr[1][1], bKR + (uint32_t)kk * 32u);
            ldsm_x4(bkp[0][0], bkp[0][1], bkp[1][0], bkp[1][1], bKP + (uint32_t)kk * 32u);
            ldsm_x4(brk[0][0], brk[0][1], brk[1][0], brk[1][1], bRK + (uint32_t)kk * 32u);

            #pragma unroll
            for (int ni = 0; ni < 2; ni++) {
                mma_tf32(A1[ni][0], A1[ni][1], A1[ni][2], A1[ni][3],
                         aqr[0], aqr[1], aqr[2], aqr[3], bkr[ni][0], bkr[ni][1]);
                mma_tf32(A2[ni][0], A2[ni][1], A2[ni][2], A2[ni][3],
                         aqp[0], aqp[1], aqp[2], aqp[3], bkp[ni][0], bkp[ni][1]);
                mma_tf32(A3[ni][0], A3[ni][1], A3[ni][2], A3[ni][3],
                         aqr[0], aqr[1], aqr[2], aqr[3], bkp[ni][0], bkp[ni][1]);
            }
            #pragma unroll
            for (int li = 0; li < 2; li++) {
                mma_tf32(B1[li][0], B1[li][1], B1[li][2], B1[li][3],
                         aqr[0], aqr[1], aqr[2], aqr[3], brk[li][0], brk[li][1]);
                mma_tf32(B2[li][0], B2[li][1], B2[li][2], B2[li][3],
                         aqp[0], aqp[1], aqp[2], aqp[3], brk[li][0], brk[li][1]);
            }
        }

        // ---- stage new E half ----
        __syncthreads();   // (a)
        #pragma unroll
        for (int li = 0; li < 2; li++) {
            #pragma unroll
            for (int q = 0; q < 4; q++) {
                int row = rloc0 + 8 * (q >> 1);
                int col = 16 * wn + 8 * li + 2 * tg + (q & 1);
                sm[ERn + row * 68 + col] = B1[li][q];
                sm[EPn + row * 68 + col] = B2[li][q];
            }
        }
        __syncthreads();   // (b)

        // ---- combine into scores (approx sqrt) ----
        float sv[2][4];
        #pragma unroll
        for (int ni = 0; ni < 2; ni++) {
            #pragma unroll
            for (int q = 0; q < 4; q++) {
                int row = rloc0 + 8 * (q >> 1);
                int col = 16 * wn + 8 * ni + 2 * tg + (q & 1);
                float wkp_c = sm[AK_WKP + col];
                float acr = A1[ni][q] + sm[AK_WKR + col] - A2[ni][q] - wkp_c;
                float acp = 2.0f * (A3[ni][q] + wkp_c);
                int L = col - row + 63;
                float bb, e1, e2;
                if (L < 64) {
                    bb = sm[AK_BRK + (nb ^ 1) * 64 + L];
                    e1 = sm[ERo + row * 68 + L];
                    e2 = sm[EPo + row * 68 + L];
                } else {
                    bb = sm[AK_BRK + nb * 64 + (L - 64)];
                    e1 = sm[ERn + row * 68 + (L - 64)];
                    e2 = sm[EPn + row * 68 + (L - 64)];
                }
                float b1v = e1 + bb;
                float b2v = e2 + bb;
                float s = (sqrt_approx(acr * acr + acp * acp)
                         + sqrt_approx(b1v * b1v + b2v * b2v)) * SCALE_F;
                if (diag && col > row) s = -1e30f;
                sv[ni][q] = s;
            }
        }

        // ---- online softmax ----
        float pm[2] = {-1e30f, -1e30f};
        #pragma unroll
        for (int ni = 0; ni < 2; ni++) {
            #pragma unroll
            for (int q = 0; q < 4; q++) pm[q >> 1] = fmaxf(pm[q >> 1], sv[ni][q]);
        }
        #pragma unroll
        for (int rh = 0; rh < 2; rh++) {
            pm[rh] = fmaxf(pm[rh], __shfl_xor_sync(0xffffffffu, pm[rh], 1));
            pm[rh] = fmaxf(pm[rh], __shfl_xor_sync(0xffffffffu, pm[rh], 2));
        }
        sm[AK_MT + wn * 64 + rloc0]     = pm[0];
        sm[AK_MT + wn * 64 + rloc0 + 8] = pm[1];
        __syncthreads();   // (c)

        float mold[2], mnew[2], alpha[2], psum[2] = {0.f, 0.f};
        #pragma unroll
        for (int rh = 0; rh < 2; rh++) {
            int r = rloc0 + 8 * rh;
            mold[rh] = sm[AK_MRUN + r];
            float mt = fmaxf(fmaxf(sm[AK_MT + r], sm[AK_MT + 64 + r]),
                             fmaxf(sm[AK_MT + 128 + r], sm[AK_MT + 192 + r]));
            mnew[rh] = fmaxf(mold[rh], mt);
            alpha[rh] = __expf(mold[rh] - mnew[rh]);
        }
        #pragma unroll
        for (int ni = 0; ni < 2; ni++) {
            #pragma unroll
            for (int q = 0; q < 4; q++) {
                int rh = q >> 1;
                int row = rloc0 + 8 * rh;
                int col = 16 * wn + 8 * ni + 2 * tg + (q & 1);
                float p = __expf(sv[ni][q] - mnew[rh]);
                psum[rh] += p;
                sm[AK_P + row * 68 + col] = p;
            }
        }
        #pragma unroll
        for (int rh = 0; rh < 2; rh++) {
            psum[rh] += __shfl_xor_sync(0xffffffffu, psum[rh], 1);
            psum[rh] += __shfl_xor_sync(0xffffffffu, psum[rh], 2);
        }
        sm[AK_LT + wn * 64 + rloc0]     = psum[0];
        sm[AK_LT + wn * 64 + rloc0 + 8] = psum[1];
        #pragma unroll
        for (int ni = 0; ni < 4; ni++) {
            #pragma unroll
            for (int q = 0; q < 4; q++) O[ni][q] *= alpha[q >> 1];
        }
        __syncthreads();   // (d)

        if (wn == 0 && tg == 0) {
            #pragma unroll
            for (int rh = 0; rh < 2; rh++) {
                int r = rloc0 + 8 * rh;
                sm[AK_MRUN + r] = mnew[rh];
                sm[AK_LRUN + r] = sm[AK_LRUN + r] * alpha[rh]
                                  + sm[AK_LT + r] + sm[AK_LT + 64 + r]
                                  + sm[AK_LT + 128 + r] + sm[AK_LT + 192 + r];
            }
        }

        // ---- PV mma: O += P(64x64) @ V(64x128), P via ldmatrix ----
        #pragma unroll
        for (int kk = 0; kk < 8; kk++) {
            uint32_t ap[4];
            ldsm_x4(ap[0], ap[1], ap[2], ap[3], aP + (uint32_t)kk * 32u);
            #pragma unroll
            for (int ni = 0; ni < 4; ni++) {
                int ch = 32 * wn + 8 * ni + g;
                uint32_t b0 = __float_as_uint(sm[AK_V + (kk * 8 + tg) * 136 + ch]);
                uint32_t b1 = __float_as_uint(sm[AK_V + (kk * 8 + tg + 4) * 136 + ch]);
                mma_tf32(O[ni][0], O[ni][1], O[ni][2], O[ni][3],
                         ap[0], ap[1], ap[2], ap[3], b0, b1);
            }
        }
    }

    __syncthreads();
    float linv[2] = {1.f / sm[AK_LRUN + rloc0], 1.f / sm[AK_LRUN + rloc0 + 8]};
    float* dst = (wn < 2) ? vecr : vecp;
    const int colbase = (32 * wn) & 63;
    #pragma unroll
    for (int ni = 0; ni < 4; ni++) {
        int ch = colbase + 8 * ni + 2 * tg;
        int r0 = i0 + rloc0;
        size_t o0 = (size_t)(r0 * 4 + b) * EDIM + n * 64 + ch;
        size_t o1 = (size_t)((r0 + 8) * 4 + b) * EDIM + n * 64 + ch;
        *(float2*)&dst[o0] = make_float2(O[ni][0] * linv[0], O[ni][1] * linv[0]);
        *(float2*)&dst[o1] = make_float2(O[ni][2] * linv[1], O[ni][3] * linv[1]);
    }
}

// ---------------- LayerNorm (vectorized, 1 global read) --------------------
__global__ void __launch_bounds__(256) ln2_kernel(
    const float* __restrict__ yr, const float* __restrict__ yp,
    const float* __restrict__ g, const float* __restrict__ be,
    float* __restrict__ out)
{
    const int row = blockIdx.x;
    const float* y = (blockIdx.y ? yp : yr) + (size_t)row * EDIM;
    float* o = out + (size_t)blockIdx.y * MB * EDIM + (size_t)row * EDIM;
    const int tid = threadIdx.x;
    const int lane = tid & 31, warp = tid >> 5;
    __shared__ float ws[8];
    __shared__ float s_mu, s_rstd;

    float4 v = ((const float4*)y)[tid];
    float s = v.x + v.y + v.z + v.w;
    #pragma unroll
    for (int off = 16; off > 0; off >>= 1) s += __shfl_xor_sync(0xffffffffu, s, off);
    if (lane == 0) ws[warp] = s;
    __syncthreads();
    if (tid == 0) {
        float t = 0.f;
        #pragma unroll
        for (int w = 0; w < 8; w++) t += ws[w];
        s_mu = t * (1.f / EDIM);
    }
    __syncthreads();
    const float mu = s_mu;

    float dx = v.x - mu, dy = v.y - mu, dz = v.z - mu, dw = v.w - mu;
    float sq = dx * dx + dy * dy + dz * dz + dw * dw;
    #pragma unroll
    for (int off = 16; off > 0; off >>= 1) sq += __shfl_xor_sync(0xffffffffu, sq, off);
    if (lane == 0) ws[warp] = sq;
    __syncthreads();
    if (tid == 0) {
        float t = 0.f;
        #pragma unroll
        for (int w = 0; w < 8; w++) t += ws[w];
        s_rstd = rsqrtf(t * (1.f / EDIM) + LN_EPS);
    }
    __syncthreads();
    const float rstd = s_rstd;

    float4 gv = ((const float4*)g)[tid];
    float4 bv = ((const float4*)be)[tid];
    float4 rr;
    rr.x = dx * rstd * gv.x + bv.x;
    rr.y = dy * rstd * gv.y + bv.y;
    rr.z = dz * rstd * gv.z + bv.z;
    rr.w = dw * rstd * gv.w + bv.w;
    ((float4*)o)[tid] = rr;
}

// ---------------- launch ---------------------------------------------------
extern "C" void kernel_launch(void* const* d_in, const int* in_sizes, int n_in,
                              void* d_out, int out_size)
{
    (void)in_sizes; (void)n_in; (void)out_size;
    const float* w_real  = (const float*)d_in[0];
    const float* w_phase = (const float*)d_in[1];
    const float* r       = (const float*)d_in[2];
    const float* r_w_b   = (const float*)d_in[3];
    const float* r_r_b   = (const float*)d_in[4];
    const float* W_qkv   = (const float*)d_in[5];
    const float* W_qkv1  = (const float*)d_in[6];
    const float* W_r     = (const float*)d_in[7];
    const float* W_o     = (const float*)d_in[8];
    const float* W_o1    = (const float*)d_in[9];
    const float* gamma   = (const float*)d_in[10];
    const float* beta    = (const float*)d_in[11];

    float *heads_r, *heads_p, *rkb, *vecr, *vecp, *yr, *yp;
    cudaGetSymbolAddress((void**)&heads_r, g_heads_r);
    cudaGetSymbolAddress((void**)&heads_p, g_heads_p);
    cudaGetSymbolAddress((void**)&rkb,     g_rk);
    cudaGetSymbolAddress((void**)&vecr,    g_vecr);
    cudaGetSymbolAddress((void**)&vecp,    g_vecp);
    cudaGetSymbolAddress((void**)&yr,      g_yr);
    cudaGetSymbolAddress((void**)&yp,      g_yp);

    cudaFuncSetAttribute(tf32_gemm_qkvr, cudaFuncAttributeMaxDynamicSharedMemorySize, GEMM_SMEM_BYTES);
    cudaFuncSetAttribute(tf32_gemm_dual, cudaFuncAttributeMaxDynamicSharedMemorySize, GEMM_SMEM_BYTES);
    cudaFuncSetAttribute(attn_fused_kernel, cudaFuncAttributeMaxDynamicSharedMemorySize, AK_SMEM_BYTES);

    // QKV projections (both streams) + r projection, single launch
    tf32_gemm_qkvr<<<dim3(HDIM / 128, MB / 128, 3), 128, GEMM_SMEM_BYTES>>>(
        w_real, w_phase, W_qkv, W_qkv1, heads_r, heads_p, r, W_r, rkb);

    // fused attention: band-reuse + approx sqrt + ldmatrix fragments
    attn_fused_kernel<<<dim3(16, 64), 512, AK_SMEM_BYTES>>>(
        heads_r, heads_p, rkb, r_w_b, r_r_b, vecr, vecp);

    // output projections with residual (both streams, one launch), then LN
    tf32_gemm_dual<<<dim3(EDIM / 128, MB / 128, 2), 128, GEMM_SMEM_BYTES>>>(
        vecr, vecp, W_o, W_o1, w_real, w_phase, yr, yp, MB, EDIM, EDIM);

    float* out = (float*)d_out;
    ln2_kernel<<<dim3(MB, 2), 256>>>(yr, yp, gamma, beta, out);
}